// round 11
// baseline (speedup 1.0000x reference)
#include <cuda_runtime.h>
#include <cuda_fp16.h>
#include <cstdint>

#define NN   50000
#define EE   800000
#define INC  128
#define OUTC 64
#define HH   4
#define KK2  512          // H * INC
#define NEG  0.2f
#define SCAN_BLOCKS ((NN + 1023) / 1024)

// -------- scratch --------
__device__ __align__(16) __half g_xhh[(size_t)NN * INC];  // x in fp16 [N][128]
__device__ __align__(16) __half g_y[(size_t)NN * KK2];    // aggregated input-space feats [N][512]
__device__ __align__(16) float  g_asrc[NN * HH];
__device__ __align__(16) float  g_adst[NN * HH];
__device__ __align__(16) float  g_watt[8 * INC];          // [j][k]: j=0..3 src head, 4..7 dst head
__device__ __align__(16) __half g_w2t[OUTC * KK2];        // [c][h*128+k] = W[k][h*64+c]
__device__ int g_deg[NN], g_loc[NN], g_off[NN], g_cur[NN];
__device__ int g_eidx[EE];
__device__ int g_bsum[SCAN_BLOCKS];

__device__ __forceinline__ void mma16(float* c, const unsigned* a, unsigned b0, unsigned b1) {
    asm("mma.sync.aligned.m16n8k16.row.col.f32.f16.f16.f32 "
        "{%0,%1,%2,%3},{%4,%5,%6,%7},{%8,%9},{%0,%1,%2,%3};"
        : "+f"(c[0]), "+f"(c[1]), "+f"(c[2]), "+f"(c[3])
        : "r"(a[0]), "r"(a[1]), "r"(a[2]), "r"(a[3]), "r"(b0), "r"(b1));
}

// -------- K_att: watt[j][k] (128 blocks x 64 thr, coalesced) --------
__global__ __launch_bounds__(64) void att_kernel(const float* __restrict__ W,
                                                 const float* __restrict__ as,
                                                 const float* __restrict__ ad) {
    __shared__ float s_as[256], s_ad[256];
    int t = threadIdx.x;
    ((float4*)s_as)[t] = ((const float4*)as)[t];
    ((float4*)s_ad)[t] = ((const float4*)ad)[t];
    __syncthreads();
    int b = blockIdx.x;   // k row
    float4 wv = ((const float4*)(W + (size_t)b * 256))[t];
    int h = t >> 4, c0 = (t & 15) * 4;
    const float* pas = s_as + h * 64 + c0;
    const float* pad = s_ad + h * 64 + c0;
    float ps = wv.x * pas[0] + wv.y * pas[1] + wv.z * pas[2] + wv.w * pas[3];
    float pd = wv.x * pad[0] + wv.y * pad[1] + wv.z * pad[2] + wv.w * pad[3];
    #pragma unroll
    for (int o = 1; o < 16; o <<= 1) {
        ps += __shfl_xor_sync(0xffffffffu, ps, o);
        pd += __shfl_xor_sync(0xffffffffu, pd, o);
    }
    if ((t & 15) == 0) {
        g_watt[h * 128 + b]       = ps;
        g_watt[(4 + h) * 128 + b] = pd;
    }
}

// -------- K_w2t: coalesced W read, scattered fp16 writes --------
__global__ __launch_bounds__(256) void w2t_kernel(const float* __restrict__ W) {
    int t = blockIdx.x * 256 + threadIdx.x;
    if (t >= OUTC * KK2) return;
    int k = t >> 8, hc = t & 255;
    int h = hc >> 6, c = hc & 63;
    g_w2t[c * 512 + h * 128 + k] = __float2half(W[t]);
}

// -------- K_logits: a_src/a_dst = x @ watt^T; store x as fp16 (warp/node) --------
__global__ __launch_bounds__(256) void logits_kernel(const float* __restrict__ x) {
    const unsigned FULL = 0xffffffffu;
    int n = (blockIdx.x * blockDim.x + threadIdx.x) >> 5;
    int lane = threadIdx.x & 31;
    if (n >= NN) return;

    float4 xv = ((const float4*)x)[(size_t)n * 32 + lane];

    float p[8];
    #pragma unroll
    for (int j = 0; j < 8; j++) {
        float4 wv = ((const float4*)g_watt)[j * 32 + lane];   // coalesced
        p[j] = xv.x * wv.x + xv.y * wv.y + xv.z * wv.z + xv.w * wv.w;
    }
    #pragma unroll
    for (int o = 1; o < 32; o <<= 1)
        #pragma unroll
        for (int j = 0; j < 8; j++)
            p[j] += __shfl_xor_sync(FULL, p[j], o);

    if (lane == 0) { g_asrc[n*4+0] = p[0]; g_adst[n*4+0] = p[4]; }
    if (lane == 1) { g_asrc[n*4+1] = p[1]; g_adst[n*4+1] = p[5]; }
    if (lane == 2) { g_asrc[n*4+2] = p[2]; g_adst[n*4+2] = p[6]; }
    if (lane == 3) { g_asrc[n*4+3] = p[3]; g_adst[n*4+3] = p[7]; }

    __half2 ha = __floats2half2_rn(xv.x, xv.y);
    __half2 hb = __floats2half2_rn(xv.z, xv.w);
    uint2 u;
    u.x = *reinterpret_cast<unsigned*>(&ha);
    u.y = *reinterpret_cast<unsigned*>(&hb);
    ((uint2*)g_xhh)[(size_t)n * 32 + lane] = u;
}

// -------- CSR build chain --------
__global__ void zero_kernel() {
    int i = blockIdx.x * blockDim.x + threadIdx.x;
    if (i < NN) g_deg[i] = 0;
}
__global__ __launch_bounds__(256) void hist_kernel(const int* __restrict__ ei) {
    int t = blockIdx.x * blockDim.x + threadIdx.x;
    if (t * 4 >= EE) return;
    int4 d4 = __ldg(reinterpret_cast<const int4*>(ei + EE) + t);
    atomicAdd(&g_deg[d4.x], 1);
    atomicAdd(&g_deg[d4.y], 1);
    atomicAdd(&g_deg[d4.z], 1);
    atomicAdd(&g_deg[d4.w], 1);
}

// -------- K_scan1: block-local scan (warp shuffles), publish block sums --------
__global__ __launch_bounds__(1024) void scan1_kernel() {
    __shared__ int s_wsum[32];
    const unsigned FULL = 0xffffffffu;
    int tid = threadIdx.x;
    int lane = tid & 31, warp = tid >> 5;
    int i = blockIdx.x * 1024 + tid;
    int v = (i < NN) ? g_deg[i] : 0;

    int incl = v;
    #pragma unroll
    for (int o = 1; o < 32; o <<= 1) {
        int t = __shfl_up_sync(FULL, incl, o);
        if (lane >= o) incl += t;
    }
    if (lane == 31) s_wsum[warp] = incl;
    __syncthreads();
    if (warp == 0) {
        int ws = s_wsum[lane];
        #pragma unroll
        for (int o = 1; o < 32; o <<= 1) {
            int t = __shfl_up_sync(FULL, ws, o);
            if (lane >= o) ws += t;
        }
        s_wsum[lane] = ws;
    }
    __syncthreads();
    int base = (warp > 0) ? s_wsum[warp - 1] : 0;
    incl += base;                    // block-inclusive

    if (i < NN) g_loc[i] = incl - v; // block-exclusive
    if (tid == 1023) g_bsum[blockIdx.x] = incl;
}

// -------- K_scan3: each block sums its predecessors' bsum inline (no spin) --------
__global__ __launch_bounds__(1024) void scan3_kernel() {
    __shared__ int s_prefix;
    const unsigned FULL = 0xffffffffu;
    int tid = threadIdx.x;
    int lane = tid & 31, warp = tid >> 5;
    int b = blockIdx.x;

    if (warp == 0) {
        int sum = 0;
        for (int k = lane; k < b; k += 32) sum += g_bsum[k];   // <= 49 values total
        #pragma unroll
        for (int o = 16; o >= 1; o >>= 1)
            sum += __shfl_xor_sync(FULL, sum, o);
        if (lane == 0) s_prefix = sum;
    }
    __syncthreads();

    int i = b * 1024 + tid;
    if (i < NN) {
        int off = s_prefix + g_loc[i];
        g_off[i] = off;
        g_cur[i] = off;
    }
}

__global__ __launch_bounds__(256) void scatter_kernel(const int* __restrict__ ei) {
    int t = blockIdx.x * blockDim.x + threadIdx.x;
    if (t * 4 >= EE) return;
    int4 s4 = __ldg(reinterpret_cast<const int4*>(ei) + t);
    int4 d4 = __ldg(reinterpret_cast<const int4*>(ei + EE) + t);
    g_eidx[atomicAdd(&g_cur[d4.x], 1)] = s4.x;
    g_eidx[atomicAdd(&g_cur[d4.y], 1)] = s4.y;
    g_eidx[atomicAdd(&g_cur[d4.z], 1)] = s4.z;
    g_eidx[atomicAdd(&g_cur[d4.w], 1)] = s4.w;
}

// -------- K_agg: input-space gather + softmax, pipelined pairs (warp/dst) --------
__global__ __launch_bounds__(256) void aggregate_kernel() {
    const unsigned FULL = 0xffffffffu;
    int d = (blockIdx.x * blockDim.x + threadIdx.x) >> 5;
    int lane = threadIdx.x & 31;
    if (d >= NN) return;

    const int off = g_off[d];
    const int jend = off + g_deg[d];

    float adh = (lane < 4) ? __ldg(g_adst + d * 4 + lane) : 0.f;

    float acc[4][4];
    #pragma unroll
    for (int h = 0; h < 4; h++)
        #pragma unroll
        for (int q = 0; q < 4; q++) acc[h][q] = 0.f;
    float den = 0.f;

    const uint2* xb = reinterpret_cast<const uint2*>(g_xhh);

    // pipeline state: current pair (s0 valid, s1 valid iff have1) with pre-issued a-loads
    int  s0 = d, s1 = d;
    int  have1 = 0;
    int  jn = off;
    if (jn < jend) { s1 = __ldg(g_eidx + jn); have1 = 1; jn++; }
    float a0 = (lane < 4) ? __ldg(g_asrc + s0 * 4 + lane) : 0.f;
    float a1 = (lane < 4) ? __ldg(g_asrc + s1 * 4 + lane) : 0.f;

    while (true) {
        // prefetch next pair (indices + logits) before consuming current
        int t0 = d, t1 = d, h0 = 0, h1 = 0;
        if (jn < jend)     { t0 = __ldg(g_eidx + jn);     h0 = 1; }
        if (jn + 1 < jend) { t1 = __ldg(g_eidx + jn + 1); h1 = 1; }
        float na0 = (lane < 4 && h0) ? __ldg(g_asrc + t0 * 4 + lane) : 0.f;
        float na1 = (lane < 4 && h1) ? __ldg(g_asrc + t1 * 4 + lane) : 0.f;

        float w0 = 0.f, w1 = 0.f;
        if (lane < 4) {
            float aa0 = a0 + adh;
            aa0 = aa0 > 0.f ? aa0 : NEG * aa0;
            w0 = __expf(aa0);
            if (have1) {
                float aa1 = a1 + adh;
                aa1 = aa1 > 0.f ? aa1 : NEG * aa1;
                w1 = __expf(aa1);
            }
            den += w0 + w1;
        }
        float b0[4], b1[4];
        #pragma unroll
        for (int h = 0; h < 4; h++) {
            b0[h] = __shfl_sync(FULL, w0, h);
            b1[h] = __shfl_sync(FULL, w1, h);
        }

        uint2 xv0 = xb[(size_t)s0 * 32 + lane];
        uint2 xv1 = xb[(size_t)s1 * 32 + lane];
        __half2 p00 = *reinterpret_cast<__half2*>(&xv0.x);
        __half2 p01 = *reinterpret_cast<__half2*>(&xv0.y);
        __half2 p10 = *reinterpret_cast<__half2*>(&xv1.x);
        __half2 p11 = *reinterpret_cast<__half2*>(&xv1.y);
        float2 f00 = __half22float2(p00), f01 = __half22float2(p01);
        float2 f10 = __half22float2(p10), f11 = __half22float2(p11);
        float f0[4] = {f00.x, f00.y, f01.x, f01.y};
        float f1[4] = {f10.x, f10.y, f11.x, f11.y};
        #pragma unroll
        for (int h = 0; h < 4; h++)
            #pragma unroll
            for (int q = 0; q < 4; q++)
                acc[h][q] = fmaf(b0[h], f0[q], fmaf(b1[h], f1[q], acc[h][q]));

        if (!h0) break;
        s0 = t0; s1 = t1; have1 = h1;
        a0 = na0; a1 = na1;
        jn += 2;
    }

    float sc = (lane < 4) ? 0.25f / den : 0.f;  // fold head-mean into normalization
    float shh[4];
    #pragma unroll
    for (int h = 0; h < 4; h++) shh[h] = __shfl_sync(FULL, sc, h);

    uint2* yb = reinterpret_cast<uint2*>(g_y);
    #pragma unroll
    for (int h = 0; h < 4; h++) {
        __half2 a = __floats2half2_rn(acc[h][0] * shh[h], acc[h][1] * shh[h]);
        __half2 b = __floats2half2_rn(acc[h][2] * shh[h], acc[h][3] * shh[h]);
        uint2 v;
        v.x = *reinterpret_cast<unsigned*>(&a);
        v.y = *reinterpret_cast<unsigned*>(&b);
        yb[(size_t)d * 128 + h * 32 + lane] = v;
    }
}

// -------- K_gemm2: out = relu(Y[50000,512] @ W2t^T + bias), fp16 mma --------
#define G2BM 128
#define G2STR 20   // u32 row stride: 16 data + 4 pad
__global__ __launch_bounds__(256) void gemm2_kernel(
    const float* __restrict__ cb, const float* __restrict__ lb, float* __restrict__ out)
{
    __shared__ __align__(16) unsigned sA[G2BM * G2STR];
    __shared__ __align__(16) unsigned sB[OUTC * G2STR];

    const int brow = blockIdx.x;
    const int tid  = threadIdx.x;
    const int lane = tid & 31, warp = tid >> 5;
    const int wm = warp >> 1, wn = warp & 1;
    const int g = lane >> 2, tig = lane & 3;

    float c[2][4][4];
    #pragma unroll
    for (int mt = 0; mt < 2; mt++)
        #pragma unroll
        for (int nt = 0; nt < 4; nt++)
            #pragma unroll
            for (int i = 0; i < 4; i++) c[mt][nt][i] = 0.f;

    const uint4* Y4 = reinterpret_cast<const uint4*>(g_y);     // row = 64 uint4
    const uint4* W4 = reinterpret_cast<const uint4*>(g_w2t);   // row = 64 uint4

    for (int kc = 0; kc < 16; kc++) {
        #pragma unroll
        for (int p = 0; p < 2; p++) {
            int idx = p * 256 + tid, r = idx >> 2, q = idx & 3;
            int d = brow * G2BM + r;
            uint4 v = make_uint4(0u, 0u, 0u, 0u);
            if (d < NN) v = Y4[(size_t)d * 64 + kc * 4 + q];
            unsigned* dst = &sA[r * G2STR + q * 4];
            dst[0] = v.x; dst[1] = v.y; dst[2] = v.z; dst[3] = v.w;
        }
        {
            int r = tid >> 2, q = tid & 3;
            uint4 v = W4[r * 64 + kc * 4 + q];
            unsigned* dst = &sB[r * G2STR + q * 4];
            dst[0] = v.x; dst[1] = v.y; dst[2] = v.z; dst[3] = v.w;
        }
        __syncthreads();

        #pragma unroll
        for (int ks = 0; ks < 2; ks++) {
            int ko = ks * 8;
            unsigned a[2][4];
            #pragma unroll
            for (int mt = 0; mt < 2; mt++) {
                int rb = wm * 32 + mt * 16;
                a[mt][0] = sA[(rb + g)     * G2STR + ko + tig];
                a[mt][1] = sA[(rb + g + 8) * G2STR + ko + tig];
                a[mt][2] = sA[(rb + g)     * G2STR + ko + tig + 4];
                a[mt][3] = sA[(rb + g + 8) * G2STR + ko + tig + 4];
            }
            #pragma unroll
            for (int nt = 0; nt < 4; nt++) {
                int n = wn * 32 + nt * 8 + g;
                unsigned b0 = sB[n * G2STR + ko + tig];
                unsigned b1 = sB[n * G2STR + ko + tig + 4];
                mma16(c[0][nt], a[0], b0, b1);
                mma16(c[1][nt], a[1], b0, b1);
            }
        }
        __syncthreads();
    }

    #pragma unroll
    for (int mt = 0; mt < 2; mt++)
        #pragma unroll
        for (int nt = 0; nt < 4; nt++) {
            int col = wn * 32 + nt * 8 + 2 * tig;
            float b0 = __ldg(cb + col)     + __ldg(lb + col);
            float b1 = __ldg(cb + col + 1) + __ldg(lb + col + 1);
            int r0 = brow * G2BM + wm * 32 + mt * 16 + g;
            float v0 = c[mt][nt][0] + b0; v0 = v0 > 0.f ? v0 : 0.f;
            float v1 = c[mt][nt][1] + b1; v1 = v1 > 0.f ? v1 : 0.f;
            if (r0 < NN)
                *reinterpret_cast<float2*>(out + (size_t)r0 * OUTC + col) = make_float2(v0, v1);
            int r1 = r0 + 8;
            float v2 = c[mt][nt][2] + b0; v2 = v2 > 0.f ? v2 : 0.f;
            float v3 = c[mt][nt][3] + b1; v3 = v3 > 0.f ? v3 : 0.f;
            if (r1 < NN)
                *reinterpret_cast<float2*>(out + (size_t)r1 * OUTC + col) = make_float2(v2, v3);
        }
}

// -------- launch --------
extern "C" void kernel_launch(void* const* d_in, const int* in_sizes, int n_in,
                              void* d_out, int out_size)
{
    const float* x     = (const float*)d_in[0];
    const int*   ei    = (const int*)  d_in[1];
    const float* w     = (const float*)d_in[2];
    const float* att_s = (const float*)d_in[3];
    const float* att_d = (const float*)d_in[4];
    const float* cb    = (const float*)d_in[5];
    const float* lb    = (const float*)d_in[6];
    float* out = (float*)d_out;

    static cudaStream_t s2 = nullptr;
    static cudaEvent_t evFork = nullptr, evCsr = nullptr, evW2t = nullptr;
    if (s2 == nullptr) {
        cudaStreamCreateWithFlags(&s2, cudaStreamNonBlocking);
        cudaEventCreateWithFlags(&evFork, cudaEventDisableTiming);
        cudaEventCreateWithFlags(&evCsr, cudaEventDisableTiming);
        cudaEventCreateWithFlags(&evW2t, cudaEventDisableTiming);
    }

    cudaEventRecord(evFork, 0);
    cudaStreamWaitEvent(s2, evFork, 0);

    // side: CSR build (zero -> hist -> scan1 -> scan3 -> scatter), then W2 transpose
    zero_kernel<<<(NN + 255) / 256, 256, 0, s2>>>();
    hist_kernel<<<(EE / 4 + 255) / 256, 256, 0, s2>>>(ei);
    scan1_kernel<<<SCAN_BLOCKS, 1024, 0, s2>>>();
    scan3_kernel<<<SCAN_BLOCKS, 1024, 0, s2>>>();
    scatter_kernel<<<(EE / 4 + 255) / 256, 256, 0, s2>>>(ei);
    cudaEventRecord(evCsr, s2);
    w2t_kernel<<<(OUTC * KK2 + 255) / 256, 256, 0, s2>>>(w);
    cudaEventRecord(evW2t, s2);

    // main: logit projections + fp16 x
    att_kernel<<<128, 64>>>(w, att_s, att_d);
    logits_kernel<<<(NN * 32 + 255) / 256, 256>>>(x);

    cudaStreamWaitEvent(0, evCsr, 0);
    aggregate_kernel<<<(NN * 32 + 255) / 256, 256>>>();
    cudaStreamWaitEvent(0, evW2t, 0);
    gemm2_kernel<<<(NN + G2BM - 1) / G2BM, 256>>>(cb, lb, out);
}

// round 13
// speedup vs baseline: 1.1076x; 1.1076x over previous
#include <cuda_runtime.h>
#include <cuda_fp16.h>
#include <cstdint>

#define NN   50000
#define EE   800000
#define INC  128
#define OUTC 64
#define HH   4
#define KK2  512          // H * INC
#define NEG  0.2f
#define SCAN_BLOCKS ((NN + 1023) / 1024)

// -------- scratch --------
__device__ __align__(16) __half g_xhh[(size_t)NN * INC];  // x in fp16 [N][128]
__device__ __align__(16) __half g_y[(size_t)NN * KK2];    // aggregated input-space feats [N][512]
__device__ __align__(16) float  g_asrc[NN * HH];
__device__ __align__(16) float  g_adst[NN * HH];
__device__ __align__(16) float  g_watt[8 * INC];          // [j][k]: j=0..3 src head, 4..7 dst head
__device__ __align__(16) __half g_w2t[OUTC * KK2];        // [c][h*128+k] = W[k][h*64+c]
__device__ int g_deg[NN], g_loc[NN], g_off[NN], g_cur[NN];
__device__ int g_eidx[EE];
__device__ int g_bsum[SCAN_BLOCKS];

__device__ __forceinline__ void mma16(float* c, const unsigned* a, unsigned b0, unsigned b1) {
    asm("mma.sync.aligned.m16n8k16.row.col.f32.f16.f16.f32 "
        "{%0,%1,%2,%3},{%4,%5,%6,%7},{%8,%9},{%0,%1,%2,%3};"
        : "+f"(c[0]), "+f"(c[1]), "+f"(c[2]), "+f"(c[3])
        : "r"(a[0]), "r"(a[1]), "r"(a[2]), "r"(a[3]), "r"(b0), "r"(b1));
}

// -------- K_att: watt[j][k] (128 blocks x 64 thr, coalesced) --------
__global__ __launch_bounds__(64) void att_kernel(const float* __restrict__ W,
                                                 const float* __restrict__ as,
                                                 const float* __restrict__ ad) {
    __shared__ float s_as[256], s_ad[256];
    int t = threadIdx.x;
    ((float4*)s_as)[t] = ((const float4*)as)[t];
    ((float4*)s_ad)[t] = ((const float4*)ad)[t];
    __syncthreads();
    int b = blockIdx.x;   // k row
    float4 wv = ((const float4*)(W + (size_t)b * 256))[t];
    int h = t >> 4, c0 = (t & 15) * 4;
    const float* pas = s_as + h * 64 + c0;
    const float* pad = s_ad + h * 64 + c0;
    float ps = wv.x * pas[0] + wv.y * pas[1] + wv.z * pas[2] + wv.w * pas[3];
    float pd = wv.x * pad[0] + wv.y * pad[1] + wv.z * pad[2] + wv.w * pad[3];
    #pragma unroll
    for (int o = 1; o < 16; o <<= 1) {
        ps += __shfl_xor_sync(0xffffffffu, ps, o);
        pd += __shfl_xor_sync(0xffffffffu, pd, o);
    }
    if ((t & 15) == 0) {
        g_watt[h * 128 + b]       = ps;
        g_watt[(4 + h) * 128 + b] = pd;
    }
}

// -------- K_w2t: coalesced W read, scattered fp16 writes --------
__global__ __launch_bounds__(256) void w2t_kernel(const float* __restrict__ W) {
    int t = blockIdx.x * 256 + threadIdx.x;
    if (t >= OUTC * KK2) return;
    int k = t >> 8, hc = t & 255;
    int h = hc >> 6, c = hc & 63;
    g_w2t[c * 512 + h * 128 + k] = __float2half(W[t]);
}

// -------- K_logits: a_src/a_dst = x @ watt^T; store x as fp16 (warp/node) --------
__global__ __launch_bounds__(256) void logits_kernel(const float* __restrict__ x) {
    const unsigned FULL = 0xffffffffu;
    int n = (blockIdx.x * blockDim.x + threadIdx.x) >> 5;
    int lane = threadIdx.x & 31;
    if (n >= NN) return;

    float4 xv = ((const float4*)x)[(size_t)n * 32 + lane];

    float p[8];
    #pragma unroll
    for (int j = 0; j < 8; j++) {
        float4 wv = ((const float4*)g_watt)[j * 32 + lane];   // coalesced
        p[j] = xv.x * wv.x + xv.y * wv.y + xv.z * wv.z + xv.w * wv.w;
    }
    #pragma unroll
    for (int o = 1; o < 32; o <<= 1)
        #pragma unroll
        for (int j = 0; j < 8; j++)
            p[j] += __shfl_xor_sync(FULL, p[j], o);

    if (lane == 0) { g_asrc[n*4+0] = p[0]; g_adst[n*4+0] = p[4]; }
    if (lane == 1) { g_asrc[n*4+1] = p[1]; g_adst[n*4+1] = p[5]; }
    if (lane == 2) { g_asrc[n*4+2] = p[2]; g_adst[n*4+2] = p[6]; }
    if (lane == 3) { g_asrc[n*4+3] = p[3]; g_adst[n*4+3] = p[7]; }

    __half2 ha = __floats2half2_rn(xv.x, xv.y);
    __half2 hb = __floats2half2_rn(xv.z, xv.w);
    uint2 u;
    u.x = *reinterpret_cast<unsigned*>(&ha);
    u.y = *reinterpret_cast<unsigned*>(&hb);
    ((uint2*)g_xhh)[(size_t)n * 32 + lane] = u;
}

// -------- CSR build chain --------
__global__ void zero_kernel() {
    int i = blockIdx.x * blockDim.x + threadIdx.x;
    if (i < NN) g_deg[i] = 0;
}
__global__ __launch_bounds__(256) void hist_kernel(const int* __restrict__ ei) {
    int t = blockIdx.x * blockDim.x + threadIdx.x;
    if (t * 4 >= EE) return;
    int4 d4 = __ldg(reinterpret_cast<const int4*>(ei + EE) + t);
    atomicAdd(&g_deg[d4.x], 1);
    atomicAdd(&g_deg[d4.y], 1);
    atomicAdd(&g_deg[d4.z], 1);
    atomicAdd(&g_deg[d4.w], 1);
}

// -------- K_scan1: block-local scan (warp shuffles), publish block sums --------
__global__ __launch_bounds__(1024) void scan1_kernel() {
    __shared__ int s_wsum[32];
    const unsigned FULL = 0xffffffffu;
    int tid = threadIdx.x;
    int lane = tid & 31, warp = tid >> 5;
    int i = blockIdx.x * 1024 + tid;
    int v = (i < NN) ? g_deg[i] : 0;

    int incl = v;
    #pragma unroll
    for (int o = 1; o < 32; o <<= 1) {
        int t = __shfl_up_sync(FULL, incl, o);
        if (lane >= o) incl += t;
    }
    if (lane == 31) s_wsum[warp] = incl;
    __syncthreads();
    if (warp == 0) {
        int ws = s_wsum[lane];
        #pragma unroll
        for (int o = 1; o < 32; o <<= 1) {
            int t = __shfl_up_sync(FULL, ws, o);
            if (lane >= o) ws += t;
        }
        s_wsum[lane] = ws;
    }
    __syncthreads();
    int base = (warp > 0) ? s_wsum[warp - 1] : 0;
    incl += base;                    // block-inclusive

    if (i < NN) g_loc[i] = incl - v; // block-exclusive
    if (tid == 1023) g_bsum[blockIdx.x] = incl;
}

// -------- K_scan3: each block sums its predecessors' bsum inline (no spin) --------
__global__ __launch_bounds__(1024) void scan3_kernel() {
    __shared__ int s_prefix;
    const unsigned FULL = 0xffffffffu;
    int tid = threadIdx.x;
    int lane = tid & 31, warp = tid >> 5;
    int b = blockIdx.x;

    if (warp == 0) {
        int sum = 0;
        for (int k = lane; k < b; k += 32) sum += g_bsum[k];   // <= 49 values total
        #pragma unroll
        for (int o = 16; o >= 1; o >>= 1)
            sum += __shfl_xor_sync(FULL, sum, o);
        if (lane == 0) s_prefix = sum;
    }
    __syncthreads();

    int i = b * 1024 + tid;
    if (i < NN) {
        int off = s_prefix + g_loc[i];
        g_off[i] = off;
        g_cur[i] = off;
    }
}

__global__ __launch_bounds__(256) void scatter_kernel(const int* __restrict__ ei) {
    int t = blockIdx.x * blockDim.x + threadIdx.x;
    if (t * 4 >= EE) return;
    int4 s4 = __ldg(reinterpret_cast<const int4*>(ei) + t);
    int4 d4 = __ldg(reinterpret_cast<const int4*>(ei + EE) + t);
    g_eidx[atomicAdd(&g_cur[d4.x], 1)] = s4.x;
    g_eidx[atomicAdd(&g_cur[d4.y], 1)] = s4.y;
    g_eidx[atomicAdd(&g_cur[d4.z], 1)] = s4.z;
    g_eidx[atomicAdd(&g_cur[d4.w], 1)] = s4.w;
}

// -------- K_agg: input-space gather + softmax, 2-way unrolled (warp/dst) --------
__global__ __launch_bounds__(256) void aggregate_kernel() {
    const unsigned FULL = 0xffffffffu;
    int d = (blockIdx.x * blockDim.x + threadIdx.x) >> 5;
    int lane = threadIdx.x & 31;
    if (d >= NN) return;

    const int off = g_off[d];
    const int jend = off + g_deg[d];

    float adh = (lane < 4) ? __ldg(g_adst + d * 4 + lane) : 0.f;

    float acc[4][4];
    #pragma unroll
    for (int h = 0; h < 4; h++)
        #pragma unroll
        for (int q = 0; q < 4; q++) acc[h][q] = 0.f;
    float den = 0.f;

    const uint2* xb = reinterpret_cast<const uint2*>(g_xhh);

    for (int j = off - 1; j < jend; j += 2) {
        int  s0 = (j < off) ? d : __ldg(g_eidx + j);
        bool v1 = (j + 1 < jend);
        int  s1 = v1 ? __ldg(g_eidx + j + 1) : s0;

        float w0 = 0.f, w1 = 0.f;
        if (lane < 4) {
            float a0 = __ldg(g_asrc + s0 * 4 + lane) + adh;
            a0 = a0 > 0.f ? a0 : NEG * a0;
            w0 = __expf(a0);
            float a1 = __ldg(g_asrc + s1 * 4 + lane) + adh;
            a1 = a1 > 0.f ? a1 : NEG * a1;
            w1 = v1 ? __expf(a1) : 0.f;
            den += w0 + w1;
        }
        float b0[4], b1[4];
        #pragma unroll
        for (int h = 0; h < 4; h++) {
            b0[h] = __shfl_sync(FULL, w0, h);
            b1[h] = __shfl_sync(FULL, w1, h);
        }

        uint2 xv0 = xb[(size_t)s0 * 32 + lane];
        uint2 xv1 = xb[(size_t)s1 * 32 + lane];
        __half2 p00 = *reinterpret_cast<__half2*>(&xv0.x);
        __half2 p01 = *reinterpret_cast<__half2*>(&xv0.y);
        __half2 p10 = *reinterpret_cast<__half2*>(&xv1.x);
        __half2 p11 = *reinterpret_cast<__half2*>(&xv1.y);
        float2 f00 = __half22float2(p00), f01 = __half22float2(p01);
        float2 f10 = __half22float2(p10), f11 = __half22float2(p11);
        float f0[4] = {f00.x, f00.y, f01.x, f01.y};
        float f1[4] = {f10.x, f10.y, f11.x, f11.y};
        #pragma unroll
        for (int h = 0; h < 4; h++)
            #pragma unroll
            for (int q = 0; q < 4; q++)
                acc[h][q] = fmaf(b0[h], f0[q], fmaf(b1[h], f1[q], acc[h][q]));
    }

    float sc = (lane < 4) ? 0.25f / den : 0.f;  // fold head-mean into normalization
    float shh[4];
    #pragma unroll
    for (int h = 0; h < 4; h++) shh[h] = __shfl_sync(FULL, sc, h);

    uint2* yb = reinterpret_cast<uint2*>(g_y);
    #pragma unroll
    for (int h = 0; h < 4; h++) {
        __half2 a = __floats2half2_rn(acc[h][0] * shh[h], acc[h][1] * shh[h]);
        __half2 b = __floats2half2_rn(acc[h][2] * shh[h], acc[h][3] * shh[h]);
        uint2 v;
        v.x = *reinterpret_cast<unsigned*>(&a);
        v.y = *reinterpret_cast<unsigned*>(&b);
        yb[(size_t)d * 128 + h * 32 + lane] = v;
    }
}

// -------- K_gemm2: out = relu(Y[50000,512] @ W2t^T + bias), fp16 mma --------
#define G2BM 128
#define G2STR 20   // u32 row stride: 16 data + 4 pad
__global__ __launch_bounds__(256) void gemm2_kernel(
    const float* __restrict__ cb, const float* __restrict__ lb, float* __restrict__ out)
{
    __shared__ __align__(16) unsigned sA[G2BM * G2STR];
    __shared__ __align__(16) unsigned sB[OUTC * G2STR];

    const int brow = blockIdx.x;
    const int tid  = threadIdx.x;
    const int lane = tid & 31, warp = tid >> 5;
    const int wm = warp >> 1, wn = warp & 1;
    const int g = lane >> 2, tig = lane & 3;

    float c[2][4][4];
    #pragma unroll
    for (int mt = 0; mt < 2; mt++)
        #pragma unroll
        for (int nt = 0; nt < 4; nt++)
            #pragma unroll
            for (int i = 0; i < 4; i++) c[mt][nt][i] = 0.f;

    const uint4* Y4 = reinterpret_cast<const uint4*>(g_y);     // row = 64 uint4
    const uint4* W4 = reinterpret_cast<const uint4*>(g_w2t);   // row = 64 uint4

    for (int kc = 0; kc < 16; kc++) {
        #pragma unroll
        for (int p = 0; p < 2; p++) {
            int idx = p * 256 + tid, r = idx >> 2, q = idx & 3;
            int d = brow * G2BM + r;
            uint4 v = make_uint4(0u, 0u, 0u, 0u);
            if (d < NN) v = Y4[(size_t)d * 64 + kc * 4 + q];
            unsigned* dst = &sA[r * G2STR + q * 4];
            dst[0] = v.x; dst[1] = v.y; dst[2] = v.z; dst[3] = v.w;
        }
        {
            int r = tid >> 2, q = tid & 3;
            uint4 v = W4[r * 64 + kc * 4 + q];
            unsigned* dst = &sB[r * G2STR + q * 4];
            dst[0] = v.x; dst[1] = v.y; dst[2] = v.z; dst[3] = v.w;
        }
        __syncthreads();

        #pragma unroll
        for (int ks = 0; ks < 2; ks++) {
            int ko = ks * 8;
            unsigned a[2][4];
            #pragma unroll
            for (int mt = 0; mt < 2; mt++) {
                int rb = wm * 32 + mt * 16;
                a[mt][0] = sA[(rb + g)     * G2STR + ko + tig];
                a[mt][1] = sA[(rb + g + 8) * G2STR + ko + tig];
                a[mt][2] = sA[(rb + g)     * G2STR + ko + tig + 4];
                a[mt][3] = sA[(rb + g + 8) * G2STR + ko + tig + 4];
            }
            #pragma unroll
            for (int nt = 0; nt < 4; nt++) {
                int n = wn * 32 + nt * 8 + g;
                unsigned b0 = sB[n * G2STR + ko + tig];
                unsigned b1 = sB[n * G2STR + ko + tig + 4];
                mma16(c[0][nt], a[0], b0, b1);
                mma16(c[1][nt], a[1], b0, b1);
            }
        }
        __syncthreads();
    }

    #pragma unroll
    for (int mt = 0; mt < 2; mt++)
        #pragma unroll
        for (int nt = 0; nt < 4; nt++) {
            int col = wn * 32 + nt * 8 + 2 * tig;
            float b0 = __ldg(cb + col)     + __ldg(lb + col);
            float b1 = __ldg(cb + col + 1) + __ldg(lb + col + 1);
            int r0 = brow * G2BM + wm * 32 + mt * 16 + g;
            float v0 = c[mt][nt][0] + b0; v0 = v0 > 0.f ? v0 : 0.f;
            float v1 = c[mt][nt][1] + b1; v1 = v1 > 0.f ? v1 : 0.f;
            if (r0 < NN)
                *reinterpret_cast<float2*>(out + (size_t)r0 * OUTC + col) = make_float2(v0, v1);
            int r1 = r0 + 8;
            float v2 = c[mt][nt][2] + b0; v2 = v2 > 0.f ? v2 : 0.f;
            float v3 = c[mt][nt][3] + b1; v3 = v3 > 0.f ? v3 : 0.f;
            if (r1 < NN)
                *reinterpret_cast<float2*>(out + (size_t)r1 * OUTC + col) = make_float2(v2, v3);
        }
}

// -------- launch --------
extern "C" void kernel_launch(void* const* d_in, const int* in_sizes, int n_in,
                              void* d_out, int out_size)
{
    const float* x     = (const float*)d_in[0];
    const int*   ei    = (const int*)  d_in[1];
    const float* w     = (const float*)d_in[2];
    const float* att_s = (const float*)d_in[3];
    const float* att_d = (const float*)d_in[4];
    const float* cb    = (const float*)d_in[5];
    const float* lb    = (const float*)d_in[6];
    float* out = (float*)d_out;

    static cudaStream_t s2 = nullptr;
    static cudaEvent_t evFork = nullptr, evCsr = nullptr, evW2t = nullptr;
    if (s2 == nullptr) {
        cudaStreamCreateWithFlags(&s2, cudaStreamNonBlocking);
        cudaEventCreateWithFlags(&evFork, cudaEventDisableTiming);
        cudaEventCreateWithFlags(&evCsr, cudaEventDisableTiming);
        cudaEventCreateWithFlags(&evW2t, cudaEventDisableTiming);
    }

    cudaEventRecord(evFork, 0);
    cudaStreamWaitEvent(s2, evFork, 0);

    // side: CSR build (zero -> hist -> scan1 -> scan3 -> scatter), then W2 transpose
    zero_kernel<<<(NN + 255) / 256, 256, 0, s2>>>();
    hist_kernel<<<(EE / 4 + 255) / 256, 256, 0, s2>>>(ei);
    scan1_kernel<<<SCAN_BLOCKS, 1024, 0, s2>>>();
    scan3_kernel<<<SCAN_BLOCKS, 1024, 0, s2>>>();
    scatter_kernel<<<(EE / 4 + 255) / 256, 256, 0, s2>>>(ei);
    cudaEventRecord(evCsr, s2);
    w2t_kernel<<<(OUTC * KK2 + 255) / 256, 256, 0, s2>>>(w);
    cudaEventRecord(evW2t, s2);

    // main: logit projections + fp16 x
    att_kernel<<<128, 64>>>(w, att_s, att_d);
    logits_kernel<<<(NN * 32 + 255) / 256, 256>>>(x);

    cudaStreamWaitEvent(0, evCsr, 0);
    aggregate_kernel<<<(NN * 32 + 255) / 256, 256>>>();
    cudaStreamWaitEvent(0, evW2t, 0);
    gemm2_kernel<<<(NN + G2BM - 1) / G2BM, 256>>>(cb, lb, out);
}

// round 14
// speedup vs baseline: 1.1392x; 1.0285x over previous
#include <cuda_runtime.h>
#include <cuda_fp16.h>
#include <cstdint>

#define NN   50000
#define EE   800000
#define INC  128
#define OUTC 64
#define HH   4
#define KK2  512          // H * INC
#define NEG  0.2f
#define SCAN_BLOCKS ((NN + 1023) / 1024)

// -------- scratch (static zero-init; cleanup_kernel restores zeros each replay) --------
__device__ __align__(16) __half g_xhh[(size_t)NN * INC];  // x in fp16 [N][128]
__device__ __align__(16) __half g_y[(size_t)NN * KK2];    // aggregated input-space feats [N][512]
__device__ __align__(16) float  g_asrc[NN * HH];
__device__ __align__(16) float  g_adst[NN * HH];
__device__ __align__(16) float  g_watt[8 * INC];          // [j][k]: j=0..3 src head, 4..7 dst head
__device__ __align__(16) __half g_w2t[OUTC * KK2];        // [c][h*128+k] = W[k][h*64+c]
__device__ int g_deg[NN], g_off[NN], g_cur[NN];
__device__ int g_eidx[EE];
__device__ int g_total;

__device__ __forceinline__ void mma16(float* c, const unsigned* a, unsigned b0, unsigned b1) {
    asm("mma.sync.aligned.m16n8k16.row.col.f32.f16.f16.f32 "
        "{%0,%1,%2,%3},{%4,%5,%6,%7},{%8,%9},{%0,%1,%2,%3};"
        : "+f"(c[0]), "+f"(c[1]), "+f"(c[2]), "+f"(c[3])
        : "r"(a[0]), "r"(a[1]), "r"(a[2]), "r"(a[3]), "r"(b0), "r"(b1));
}

// -------- K_att: watt[j][k] (128 blocks x 64 thr, coalesced) --------
__global__ __launch_bounds__(64) void att_kernel(const float* __restrict__ W,
                                                 const float* __restrict__ as,
                                                 const float* __restrict__ ad) {
    __shared__ float s_as[256], s_ad[256];
    int t = threadIdx.x;
    ((float4*)s_as)[t] = ((const float4*)as)[t];
    ((float4*)s_ad)[t] = ((const float4*)ad)[t];
    __syncthreads();
    int b = blockIdx.x;   // k row
    float4 wv = ((const float4*)(W + (size_t)b * 256))[t];
    int h = t >> 4, c0 = (t & 15) * 4;
    const float* pas = s_as + h * 64 + c0;
    const float* pad = s_ad + h * 64 + c0;
    float ps = wv.x * pas[0] + wv.y * pas[1] + wv.z * pas[2] + wv.w * pas[3];
    float pd = wv.x * pad[0] + wv.y * pad[1] + wv.z * pad[2] + wv.w * pad[3];
    #pragma unroll
    for (int o = 1; o < 16; o <<= 1) {
        ps += __shfl_xor_sync(0xffffffffu, ps, o);
        pd += __shfl_xor_sync(0xffffffffu, pd, o);
    }
    if ((t & 15) == 0) {
        g_watt[h * 128 + b]       = ps;
        g_watt[(4 + h) * 128 + b] = pd;
    }
}

// -------- K_w2t: coalesced W read, scattered fp16 writes --------
__global__ __launch_bounds__(256) void w2t_kernel(const float* __restrict__ W) {
    int t = blockIdx.x * 256 + threadIdx.x;
    if (t >= OUTC * KK2) return;
    int k = t >> 8, hc = t & 255;
    int h = hc >> 6, c = hc & 63;
    g_w2t[c * 512 + h * 128 + k] = __float2half(W[t]);
}

// -------- K_logits: a_src/a_dst = x @ watt^T; store x as fp16 (warp/node) --------
__global__ __launch_bounds__(256) void logits_kernel(const float* __restrict__ x) {
    const unsigned FULL = 0xffffffffu;
    int n = (blockIdx.x * blockDim.x + threadIdx.x) >> 5;
    int lane = threadIdx.x & 31;
    if (n >= NN) return;

    float4 xv = ((const float4*)x)[(size_t)n * 32 + lane];

    float p[8];
    #pragma unroll
    for (int j = 0; j < 8; j++) {
        float4 wv = ((const float4*)g_watt)[j * 32 + lane];   // coalesced
        p[j] = xv.x * wv.x + xv.y * wv.y + xv.z * wv.z + xv.w * wv.w;
    }
    #pragma unroll
    for (int o = 1; o < 32; o <<= 1)
        #pragma unroll
        for (int j = 0; j < 8; j++)
            p[j] += __shfl_xor_sync(FULL, p[j], o);

    if (lane == 0) { g_asrc[n*4+0] = p[0]; g_adst[n*4+0] = p[4]; }
    if (lane == 1) { g_asrc[n*4+1] = p[1]; g_adst[n*4+1] = p[5]; }
    if (lane == 2) { g_asrc[n*4+2] = p[2]; g_adst[n*4+2] = p[6]; }
    if (lane == 3) { g_asrc[n*4+3] = p[3]; g_adst[n*4+3] = p[7]; }

    __half2 ha = __floats2half2_rn(xv.x, xv.y);
    __half2 hb = __floats2half2_rn(xv.z, xv.w);
    uint2 u;
    u.x = *reinterpret_cast<unsigned*>(&ha);
    u.y = *reinterpret_cast<unsigned*>(&hb);
    ((uint2*)g_xhh)[(size_t)n * 32 + lane] = u;
}

// -------- K_hist: in-degree histogram (4 edges/thread); g_deg pre-zeroed --------
__global__ __launch_bounds__(256) void hist_kernel(const int* __restrict__ ei) {
    int t = blockIdx.x * blockDim.x + threadIdx.x;
    if (t * 4 >= EE) return;
    int4 d4 = __ldg(reinterpret_cast<const int4*>(ei + EE) + t);
    atomicAdd(&g_deg[d4.x], 1);
    atomicAdd(&g_deg[d4.y], 1);
    atomicAdd(&g_deg[d4.z], 1);
    atomicAdd(&g_deg[d4.w], 1);
}

// -------- K_scanfuse: block scan + atomic base (CSR slot order is irrelevant) --------
__global__ __launch_bounds__(1024) void scanfuse_kernel() {
    __shared__ int s_wsum[32];
    __shared__ int s_base;
    const unsigned FULL = 0xffffffffu;
    int tid = threadIdx.x;
    int lane = tid & 31, warp = tid >> 5;
    int i = blockIdx.x * 1024 + tid;
    int v = (i < NN) ? g_deg[i] : 0;

    int incl = v;
    #pragma unroll
    for (int o = 1; o < 32; o <<= 1) {
        int t = __shfl_up_sync(FULL, incl, o);
        if (lane >= o) incl += t;
    }
    if (lane == 31) s_wsum[warp] = incl;
    __syncthreads();
    if (warp == 0) {
        int ws = s_wsum[lane];
        #pragma unroll
        for (int o = 1; o < 32; o <<= 1) {
            int t = __shfl_up_sync(FULL, ws, o);
            if (lane >= o) ws += t;
        }
        s_wsum[lane] = ws;
    }
    __syncthreads();
    int base = (warp > 0) ? s_wsum[warp - 1] : 0;
    incl += base;                    // block-inclusive
    if (tid == 0) s_base = atomicAdd(&g_total, s_wsum[31]);
    __syncthreads();

    if (i < NN) {
        int off = s_base + incl - v;
        g_off[i] = off;
        g_cur[i] = off;
    }
}

__global__ __launch_bounds__(256) void scatter_kernel(const int* __restrict__ ei) {
    int t = blockIdx.x * blockDim.x + threadIdx.x;
    if (t * 4 >= EE) return;
    int4 s4 = __ldg(reinterpret_cast<const int4*>(ei) + t);
    int4 d4 = __ldg(reinterpret_cast<const int4*>(ei + EE) + t);
    g_eidx[atomicAdd(&g_cur[d4.x], 1)] = s4.x;
    g_eidx[atomicAdd(&g_cur[d4.y], 1)] = s4.y;
    g_eidx[atomicAdd(&g_cur[d4.z], 1)] = s4.z;
    g_eidx[atomicAdd(&g_cur[d4.w], 1)] = s4.w;
}

// -------- K_cleanup: restore scratch zeros for the next graph replay --------
__global__ __launch_bounds__(256) void cleanup_kernel() {
    int i = blockIdx.x * blockDim.x + threadIdx.x;
    if (i < NN) g_deg[i] = 0;
    if (i == 0) g_total = 0;
}

// -------- K_agg: input-space gather + softmax, 2-way unrolled (warp/dst) --------
__global__ __launch_bounds__(256) void aggregate_kernel() {
    const unsigned FULL = 0xffffffffu;
    int d = (blockIdx.x * blockDim.x + threadIdx.x) >> 5;
    int lane = threadIdx.x & 31;
    if (d >= NN) return;

    const int off = g_off[d];
    const int jend = off + g_deg[d];

    float adh = (lane < 4) ? __ldg(g_adst + d * 4 + lane) : 0.f;

    float acc[4][4];
    #pragma unroll
    for (int h = 0; h < 4; h++)
        #pragma unroll
        for (int q = 0; q < 4; q++) acc[h][q] = 0.f;
    float den = 0.f;

    const uint2* xb = reinterpret_cast<const uint2*>(g_xhh);

    for (int j = off - 1; j < jend; j += 2) {
        int  s0 = (j < off) ? d : __ldg(g_eidx + j);
        bool v1 = (j + 1 < jend);
        int  s1 = v1 ? __ldg(g_eidx + j + 1) : s0;

        float w0 = 0.f, w1 = 0.f;
        if (lane < 4) {
            float a0 = __ldg(g_asrc + s0 * 4 + lane) + adh;
            a0 = a0 > 0.f ? a0 : NEG * a0;
            w0 = __expf(a0);
            float a1 = __ldg(g_asrc + s1 * 4 + lane) + adh;
            a1 = a1 > 0.f ? a1 : NEG * a1;
            w1 = v1 ? __expf(a1) : 0.f;
            den += w0 + w1;
        }
        float b0[4], b1[4];
        #pragma unroll
        for (int h = 0; h < 4; h++) {
            b0[h] = __shfl_sync(FULL, w0, h);
            b1[h] = __shfl_sync(FULL, w1, h);
        }

        uint2 xv0 = xb[(size_t)s0 * 32 + lane];
        uint2 xv1 = xb[(size_t)s1 * 32 + lane];
        __half2 p00 = *reinterpret_cast<__half2*>(&xv0.x);
        __half2 p01 = *reinterpret_cast<__half2*>(&xv0.y);
        __half2 p10 = *reinterpret_cast<__half2*>(&xv1.x);
        __half2 p11 = *reinterpret_cast<__half2*>(&xv1.y);
        float2 f00 = __half22float2(p00), f01 = __half22float2(p01);
        float2 f10 = __half22float2(p10), f11 = __half22float2(p11);
        float f0[4] = {f00.x, f00.y, f01.x, f01.y};
        float f1[4] = {f10.x, f10.y, f11.x, f11.y};
        #pragma unroll
        for (int h = 0; h < 4; h++)
            #pragma unroll
            for (int q = 0; q < 4; q++)
                acc[h][q] = fmaf(b0[h], f0[q], fmaf(b1[h], f1[q], acc[h][q]));
    }

    float sc = (lane < 4) ? 0.25f / den : 0.f;  // fold head-mean into normalization
    float shh[4];
    #pragma unroll
    for (int h = 0; h < 4; h++) shh[h] = __shfl_sync(FULL, sc, h);

    uint2* yb = reinterpret_cast<uint2*>(g_y);
    #pragma unroll
    for (int h = 0; h < 4; h++) {
        __half2 a = __floats2half2_rn(acc[h][0] * shh[h], acc[h][1] * shh[h]);
        __half2 b = __floats2half2_rn(acc[h][2] * shh[h], acc[h][3] * shh[h]);
        uint2 v;
        v.x = *reinterpret_cast<unsigned*>(&a);
        v.y = *reinterpret_cast<unsigned*>(&b);
        yb[(size_t)d * 128 + h * 32 + lane] = v;
    }
}

// -------- K_gemm2: out = relu(Y[50000,512] @ W2t^T + bias), fp16 mma --------
#define G2BM 128
#define G2STR 20   // u32 row stride: 16 data + 4 pad
__global__ __launch_bounds__(256) void gemm2_kernel(
    const float* __restrict__ cb, const float* __restrict__ lb, float* __restrict__ out)
{
    __shared__ __align__(16) unsigned sA[G2BM * G2STR];
    __shared__ __align__(16) unsigned sB[OUTC * G2STR];

    const int brow = blockIdx.x;
    const int tid  = threadIdx.x;
    const int lane = tid & 31, warp = tid >> 5;
    const int wm = warp >> 1, wn = warp & 1;
    const int g = lane >> 2, tig = lane & 3;

    float c[2][4][4];
    #pragma unroll
    for (int mt = 0; mt < 2; mt++)
        #pragma unroll
        for (int nt = 0; nt < 4; nt++)
            #pragma unroll
            for (int i = 0; i < 4; i++) c[mt][nt][i] = 0.f;

    const uint4* Y4 = reinterpret_cast<const uint4*>(g_y);     // row = 64 uint4
    const uint4* W4 = reinterpret_cast<const uint4*>(g_w2t);   // row = 64 uint4

    for (int kc = 0; kc < 16; kc++) {
        #pragma unroll
        for (int p = 0; p < 2; p++) {
            int idx = p * 256 + tid, r = idx >> 2, q = idx & 3;
            int d = brow * G2BM + r;
            uint4 v = make_uint4(0u, 0u, 0u, 0u);
            if (d < NN) v = Y4[(size_t)d * 64 + kc * 4 + q];
            unsigned* dst = &sA[r * G2STR + q * 4];
            dst[0] = v.x; dst[1] = v.y; dst[2] = v.z; dst[3] = v.w;
        }
        {
            int r = tid >> 2, q = tid & 3;
            uint4 v = W4[r * 64 + kc * 4 + q];
            unsigned* dst = &sB[r * G2STR + q * 4];
            dst[0] = v.x; dst[1] = v.y; dst[2] = v.z; dst[3] = v.w;
        }
        __syncthreads();

        #pragma unroll
        for (int ks = 0; ks < 2; ks++) {
            int ko = ks * 8;
            unsigned a[2][4];
            #pragma unroll
            for (int mt = 0; mt < 2; mt++) {
                int rb = wm * 32 + mt * 16;
                a[mt][0] = sA[(rb + g)     * G2STR + ko + tig];
                a[mt][1] = sA[(rb + g + 8) * G2STR + ko + tig];
                a[mt][2] = sA[(rb + g)     * G2STR + ko + tig + 4];
                a[mt][3] = sA[(rb + g + 8) * G2STR + ko + tig + 4];
            }
            #pragma unroll
            for (int nt = 0; nt < 4; nt++) {
                int n = wn * 32 + nt * 8 + g;
                unsigned b0 = sB[n * G2STR + ko + tig];
                unsigned b1 = sB[n * G2STR + ko + tig + 4];
                mma16(c[0][nt], a[0], b0, b1);
                mma16(c[1][nt], a[1], b0, b1);
            }
        }
        __syncthreads();
    }

    #pragma unroll
    for (int mt = 0; mt < 2; mt++)
        #pragma unroll
        for (int nt = 0; nt < 4; nt++) {
            int col = wn * 32 + nt * 8 + 2 * tig;
            float b0 = __ldg(cb + col)     + __ldg(lb + col);
            float b1 = __ldg(cb + col + 1) + __ldg(lb + col + 1);
            int r0 = brow * G2BM + wm * 32 + mt * 16 + g;
            float v0 = c[mt][nt][0] + b0; v0 = v0 > 0.f ? v0 : 0.f;
            float v1 = c[mt][nt][1] + b1; v1 = v1 > 0.f ? v1 : 0.f;
            if (r0 < NN)
                *reinterpret_cast<float2*>(out + (size_t)r0 * OUTC + col) = make_float2(v0, v1);
            int r1 = r0 + 8;
            float v2 = c[mt][nt][2] + b0; v2 = v2 > 0.f ? v2 : 0.f;
            float v3 = c[mt][nt][3] + b1; v3 = v3 > 0.f ? v3 : 0.f;
            if (r1 < NN)
                *reinterpret_cast<float2*>(out + (size_t)r1 * OUTC + col) = make_float2(v2, v3);
        }
}

// -------- launch --------
extern "C" void kernel_launch(void* const* d_in, const int* in_sizes, int n_in,
                              void* d_out, int out_size)
{
    const float* x     = (const float*)d_in[0];
    const int*   ei    = (const int*)  d_in[1];
    const float* w     = (const float*)d_in[2];
    const float* att_s = (const float*)d_in[3];
    const float* att_d = (const float*)d_in[4];
    const float* cb    = (const float*)d_in[5];
    const float* lb    = (const float*)d_in[6];
    float* out = (float*)d_out;

    static cudaStream_t s2 = nullptr;
    static cudaEvent_t evFork = nullptr, evCsr = nullptr, evW2t = nullptr,
                       evAgg = nullptr, evClean = nullptr;
    if (s2 == nullptr) {
        cudaStreamCreateWithFlags(&s2, cudaStreamNonBlocking);
        cudaEventCreateWithFlags(&evFork, cudaEventDisableTiming);
        cudaEventCreateWithFlags(&evCsr, cudaEventDisableTiming);
        cudaEventCreateWithFlags(&evW2t, cudaEventDisableTiming);
        cudaEventCreateWithFlags(&evAgg, cudaEventDisableTiming);
        cudaEventCreateWithFlags(&evClean, cudaEventDisableTiming);
    }

    cudaEventRecord(evFork, 0);
    cudaStreamWaitEvent(s2, evFork, 0);

    // side: CSR build (hist -> scanfuse -> scatter; g_deg/g_total already zero)
    hist_kernel<<<(EE / 4 + 255) / 256, 256, 0, s2>>>(ei);
    scanfuse_kernel<<<SCAN_BLOCKS, 1024, 0, s2>>>();
    scatter_kernel<<<(EE / 4 + 255) / 256, 256, 0, s2>>>(ei);
    cudaEventRecord(evCsr, s2);
    w2t_kernel<<<(OUTC * KK2 + 255) / 256, 256, 0, s2>>>(w);
    cudaEventRecord(evW2t, s2);

    // main: logit projections + fp16 x
    att_kernel<<<128, 64>>>(w, att_s, att_d);
    logits_kernel<<<(NN * 32 + 255) / 256, 256>>>(x);

    cudaStreamWaitEvent(0, evCsr, 0);
    aggregate_kernel<<<(NN * 32 + 255) / 256, 256>>>();
    cudaEventRecord(evAgg, 0);

    // side: after aggregate consumed g_deg/g_off, re-zero for next replay (overlaps gemm2)
    cudaStreamWaitEvent(s2, evAgg, 0);
    cleanup_kernel<<<(NN + 255) / 256, 256, 0, s2>>>();
    cudaEventRecord(evClean, s2);

    cudaStreamWaitEvent(0, evW2t, 0);
    gemm2_kernel<<<(NN + G2BM - 1) / G2BM, 256>>>(cb, lb, out);
    cudaStreamWaitEvent(0, evClean, 0);
}